// round 12
// baseline (speedup 1.0000x reference)
#include <cuda_runtime.h>
#include <cstdint>
#include <cmath>

#define BATCH 16384
#define NV 1024
#define NH 1024
#define HD 64
#define KSTEPS 10

__device__ float    g_bmod[(size_t)BATCH * NV];
__device__ float    g_cmod[(size_t)BATCH * NH];
__device__ float    g_a   [(size_t)BATCH * NV];   // vW of v_model (MODE 4)
__device__ float    g_vwd [(size_t)BATCH * NV];   // recovered v_data@W for FE-data
__device__ int8_t   g_v8  [(size_t)BATCH * NV];   // v_data, then vbn chain state (binary)
__device__ int8_t   g_h8  [(size_t)BATCH * NH];   // h samples (binary)
__device__ float    g_u   [BATCH];                // u0 only (loss is u-invariant)
__device__ int8_t   g_Wq1[NV*NH], g_Wq2[NV*NH], g_Wq3[NV*NH];  // [v][h]
__device__ int8_t   g_Tq1[NV*NH], g_Tq2[NV*NH], g_Tq3[NV*NH];  // [h][v]
__device__ float    g_colsum[NH];
__device__ unsigned g_maxbits;      // max|W| as float bits (positive)
__device__ double   g_acc;

__host__ __device__ __forceinline__ void tf2x32(uint32_t k0, uint32_t k1,
                                                uint32_t x0, uint32_t x1,
                                                uint32_t& o0, uint32_t& o1) {
  uint32_t ks2 = k0 ^ k1 ^ 0x1BD11BDAu;
#define TF_R(r) { x0 += x1; x1 = (x1 << (r)) | (x1 >> (32 - (r))); x1 ^= x0; }
  x0 += k0; x1 += k1;
  TF_R(13) TF_R(15) TF_R(26) TF_R(6)   x0 += k1;  x1 += ks2 + 1u;
  TF_R(17) TF_R(29) TF_R(16) TF_R(24)  x0 += ks2; x1 += k0 + 2u;
  TF_R(13) TF_R(15) TF_R(26) TF_R(6)   x0 += k0;  x1 += k1 + 3u;
  TF_R(17) TF_R(29) TF_R(16) TF_R(24)  x0 += k1;  x1 += ks2 + 4u;
  TF_R(13) TF_R(15) TF_R(26) TF_R(6)   x0 += ks2; x1 += k0 + 5u;
#undef TF_R
  o0 = x0; o1 = x1;
}
__device__ __forceinline__ float jax_uniform(uint32_t ka, uint32_t kb, uint32_t idx) {
  uint32_t o0, o1; tf2x32(ka, kb, 0u, idx, o0, o1);
  return __uint_as_float(((o0 ^ o1) >> 9) | 0x3f800000u) - 1.0f;
}
__device__ __forceinline__ float sigmoidf_(float x)  { return 1.0f / (1.0f + expf(-x)); }
__device__ __forceinline__ float softplusf_(float x) { return fmaxf(x, 0.0f) + log1pf(expf(-fabsf(x))); }

__device__ __forceinline__ uint32_t smem_to_u32(const void* p) {
  uint32_t a;
  asm("{ .reg .u64 t; cvta.to.shared.u64 t, %1; cvt.u32.u64 %0, t; }" : "=r"(a) : "l"(p));
  return a;
}
__device__ __forceinline__ uint32_t lds32(uint32_t a) {
  uint32_t v; asm volatile("ld.shared.b32 %0, [%1];" : "=r"(v) : "r"(a)); return v;
}
__device__ __forceinline__ void sts128(uint32_t a, uint4 v) {
  asm volatile("st.shared.v4.b32 [%0], {%1,%2,%3,%4};" :: "r"(a), "r"(v.x), "r"(v.y), "r"(v.z), "r"(v.w) : "memory");
}
__device__ __forceinline__ void mma_s8(int* c, const uint32_t* a, const uint32_t* b) {
  asm volatile("mma.sync.aligned.m16n8k32.row.col.s32.s8.s8.s32 "
    "{%0,%1,%2,%3}, {%4,%5,%6,%7}, {%8,%9}, {%0,%1,%2,%3};"
    : "+r"(c[0]), "+r"(c[1]), "+r"(c[2]), "+r"(c[3])
    : "r"(a[0]), "r"(a[1]), "r"(a[2]), "r"(a[3]), "r"(b[0]), "r"(b[1]));
}

// ---------------- int8 3-plane mma GEMM ----------------
// C = A(binary) @ (s1*Q1 + s2*Q2 + s3*Q3), tile 128x128, plane-major, exact int32 accum
// 512 thr, 16 warps (4M x 4N), warp tile 32x32. 48 chunks = 3 planes x 16 kbk(64B).
// MODE 1: A=g_v8 (FLIP: xor u0), B=Tq -> sample h into g_h8 (S0: recover vdata@W -> g_vwd)
// MODE 2: A=g_h8, B=Wq -> sample vbn into g_v8 (reads g_bmod)
// MODE 4: A=g_v8, B=Tq -> write g_a (for FE-model)
#define QSTR 80
#define TILE_Q (128 * QSTR)            // 10240
#define SMQ_TOTAL (4 * TILE_Q)         // 40960: A0,A1,B0,B1

template<int MODE, bool S0, bool FLIP>
__global__ void __launch_bounds__(512, 1) gemm_i8(uint32_t ka, uint32_t kb) {
  extern __shared__ char smem[];
  uint32_t sbase = smem_to_u32(smem);
  int tid = threadIdx.x, lane = tid & 31, wid = tid >> 5;
  int wm = wid & 3, wn = wid >> 2;            // 4(M) x 4(N)
  int gq = lane >> 2, tg = lane & 3;
  int bm = blockIdx.y * 128, bn = blockIdx.x * 128;

  const int8_t* A = (MODE == 2) ? g_h8 : g_v8;
  const int8_t* Bp[3];
  if (MODE == 2) { Bp[0] = g_Wq1; Bp[1] = g_Wq2; Bp[2] = g_Wq3; }
  else           { Bp[0] = g_Tq1; Bp[1] = g_Tq2; Bp[2] = g_Tq3; }
  float M = __uint_as_float(g_maxbits);
  float s1 = M / 127.f, s2 = s1 / 250.f, s3 = s2 / 250.f;
  float sp[3] = {s1, s2, s3};

  int arow = tid >> 2, aseg = tid & 3;        // 128 rows x 4 x 16B = 64B/row chunk
  uint32_t uxr = 0;
  if (FLIP) uxr = (g_u[bm + arow] == 0.0f) ? 0x01010101u : 0u;

  uint4 areg;
  auto ldgA = [&](int c) {
    int kin = (c & 15) * 64;
    uint4 v = *(const uint4*)(A + (((size_t)(bm + arow)) << 10) + kin + aseg * 16);
    if (FLIP) { v.x ^= uxr; v.y ^= uxr; v.z ^= uxr; v.w ^= uxr; }
    areg = v;
  };
  auto stsA = [&](int buf) {
    sts128(sbase + buf * TILE_Q + arow * QSTR + aseg * 16, areg);
  };
  auto issueB = [&](int c) {
    int plane = c >> 4, kin = (c & 15) * 64, buf = c & 1;
    uint32_t dst = sbase + (2 + buf) * TILE_Q + arow * QSTR + aseg * 16;
    const void* src = (const void*)(Bp[plane] + (((size_t)(bn + arow)) << 10) + kin + aseg * 16);
    asm volatile("cp.async.cg.shared.global [%0], [%1], 16;" :: "r"(dst), "l"(src) : "memory");
    asm volatile("cp.async.commit_group;" ::: "memory");
  };

  float accf[2][4][4];
  int   acci[2][4][4];
#pragma unroll
  for (int i = 0; i < 2; i++)
#pragma unroll
    for (int j = 0; j < 4; j++)
#pragma unroll
      for (int q = 0; q < 4; q++) { accf[i][j][q] = 0.f; acci[i][j][q] = 0; }

  // prologue
  ldgA(0); stsA(0);
  issueB(0);
  ldgA(1);

  for (int c = 0; c < 48; c++) {
    if (c + 1 < 48) { issueB(c + 1); asm volatile("cp.async.wait_group 1;" ::: "memory"); }
    else            { asm volatile("cp.async.wait_group 0;" ::: "memory"); }
    __syncthreads();
    if (c + 1 < 48) stsA((c + 1) & 1);
    if (c + 2 < 48) ldgA(c + 2);

    uint32_t Ab = sbase + (c & 1) * TILE_Q;
    uint32_t Bb = sbase + (2 + (c & 1)) * TILE_Q;
#pragma unroll
    for (int ks = 0; ks < 2; ks++) {          // two k32 steps per 64B chunk
      uint32_t af[2][4];
#pragma unroll
      for (int i = 0; i < 2; i++) {
        uint32_t rb = Ab + (uint32_t)(wm * 32 + i * 16 + gq) * QSTR + ks * 32 + tg * 4;
        af[i][0] = lds32(rb);
        af[i][1] = lds32(rb + 8 * QSTR);
        af[i][2] = lds32(rb + 16);
        af[i][3] = lds32(rb + 8 * QSTR + 16);
      }
      uint32_t bf[4][2];
#pragma unroll
      for (int j = 0; j < 4; j++) {
        uint32_t cb = Bb + (uint32_t)(wn * 32 + j * 8 + gq) * QSTR + ks * 32 + tg * 4;
        bf[j][0] = lds32(cb);
        bf[j][1] = lds32(cb + 16);
      }
#pragma unroll
      for (int i = 0; i < 2; i++)
#pragma unroll
        for (int j = 0; j < 4; j++)
          mma_s8(acci[i][j], af[i], bf[j]);
    }
    if ((c & 15) == 15) {                     // end of plane: merge exact int sums
      float s = sp[c >> 4];
#pragma unroll
      for (int i = 0; i < 2; i++)
#pragma unroll
        for (int j = 0; j < 4; j++)
#pragma unroll
          for (int q = 0; q < 4; q++) { accf[i][j][q] += s * (float)acci[i][j][q]; acci[i][j][q] = 0; }
    }
    __syncthreads();
  }

  // epilogue
#pragma unroll
  for (int i = 0; i < 2; i++) {
    int row0 = bm + wm * 32 + i * 16 + gq;
#pragma unroll
    for (int j = 0; j < 4; j++) {
      int col = bn + wn * 32 + j * 8 + tg * 2;
#pragma unroll
      for (int half = 0; half < 2; half++) {
        int r = row0 + half * 8;
        uint32_t idx = ((uint32_t)r << 10) | (uint32_t)col;
        float v0 = accf[i][j][half * 2], v1 = accf[i][j][half * 2 + 1];
        if (MODE == 1) {
          if (S0) {   // recover vdata@W: u=1 -> D ; u=0 -> colsum - D
            float uu = g_u[r];
            float w0 = (uu != 0.0f) ? v0 : g_colsum[col]     - v0;
            float w1 = (uu != 0.0f) ? v1 : g_colsum[col + 1] - v1;
            *(float2*)(g_vwd + idx) = make_float2(w0, w1);
          }
          float2 cm = *(const float2*)(g_cmod + idx);
          float p0 = sigmoidf_(v0 + cm.x), p1 = sigmoidf_(v1 + cm.y);
          float u0 = jax_uniform(ka, kb, idx), u1 = jax_uniform(ka, kb, idx + 1);
          unsigned short hv = (unsigned short)((u0 < p0) ? 1 : 0) |
                              ((unsigned short)((u1 < p1) ? 1 : 0) << 8);
          *(unsigned short*)(g_h8 + idx) = hv;
        } else if (MODE == 2) {
          float2 bm2 = *(const float2*)(g_bmod + idx);
          float p0 = sigmoidf_(v0 + bm2.x), p1 = sigmoidf_(v1 + bm2.y);
          float u0 = jax_uniform(ka, kb, idx), u1 = jax_uniform(ka, kb, idx + 1);
          unsigned short vv = (unsigned short)((u0 < p0) ? 1 : 0) |
                              ((unsigned short)((u1 < p1) ? 1 : 0) << 8);
          *(unsigned short*)(g_v8 + idx) = vv;
        } else {
          *(float2*)(g_a + idx) = make_float2(v0, v1);
        }
      }
    }
  }
}

// ---- hypernetwork biases ----
#define BT_ROWS 16
__global__ void biases_kernel(const float* __restrict__ cond, const float* __restrict__ b,
                              const float* __restrict__ c, const float* __restrict__ fc1w,
                              const float* __restrict__ fc1b, const float* __restrict__ fc2w,
                              const float* __restrict__ fc2b) {
  __shared__ float xs[BT_ROWS][HD];
  int r0 = blockIdx.x * BT_ROWS, tid = threadIdx.x;
  for (int t = tid; t < BT_ROWS * HD; t += blockDim.x) {
    int r = t / HD, d = t % HD;
    xs[r][d] = tanhf(cond[r0 + r] * fc1w[d] + fc1b[d]);
  }
  __syncthreads();
  for (int j = tid; j < NV + NH; j += blockDim.x) {
    int gw, bw;
    if (j < NV) { gw = j; bw = NV + j; } else { gw = 2*NV + (j-NV); bw = 2*NV + NH + (j-NV); }
    const float* wg = fc2w + (size_t)gw * HD;
    const float* wb = fc2w + (size_t)bw * HD;
    float accG[BT_ROWS], accB[BT_ROWS];
#pragma unroll
    for (int r = 0; r < BT_ROWS; r++) { accG[r] = 0.f; accB[r] = 0.f; }
    for (int d = 0; d < HD; d++) {
      float g = wg[d], bb = wb[d];
#pragma unroll
      for (int r = 0; r < BT_ROWS; r++) { float x = xs[r][d]; accG[r] += g*x; accB[r] += bb*x; }
    }
    float gb = fc2b[gw], bbia = fc2b[bw];
    if (j < NV) {
      float bj = b[j];
      for (int r = 0; r < BT_ROWS; r++)
        g_bmod[(size_t)(r0 + r)*NV + j] = (1.0f + accG[r] + gb)*bj + (accB[r] + bbia);
    } else {
      int hh = j - NV; float ch = c[hh];
      for (int r = 0; r < BT_ROWS; r++)
        g_cmod[(size_t)(r0 + r)*NH + hh] = (1.0f + accG[r] + gb)*ch + (accB[r] + bbia);
    }
  }
}

// ---- max|W| (atomicMax on positive-float bits; idempotent across graph replays) ----
__global__ void maxabs_kernel(const float* __restrict__ W) {
  int i = blockIdx.x * blockDim.x + threadIdx.x;
  float v = fabsf(W[i]);
#pragma unroll
  for (int o = 16; o > 0; o >>= 1) v = fmaxf(v, __shfl_down_sync(0xffffffffu, v, o));
  if ((threadIdx.x & 31) == 0) atomicMax(&g_maxbits, __float_as_uint(v));
}

// ---- W 3-plane int8 quantization, both layouts ----
__device__ __forceinline__ void quant3(float w, float s1, float s2, float s3,
                                       int8_t& q1, int8_t& q2, int8_t& q3) {
  int a = (int)lrintf(w / s1);  float r1 = w - s1 * (float)a;
  int b = (int)lrintf(r1 / s2); float r2 = r1 - s2 * (float)b;
  int c = (int)lrintf(r2 / s3);
  q1 = (int8_t)a; q2 = (int8_t)b; q3 = (int8_t)c;
}
__global__ void splitq_kernel(const float* __restrict__ W) {
  __shared__ float t[32][33];
  float M = __uint_as_float(g_maxbits);
  float s1 = M / 127.f, s2 = s1 / 250.f, s3 = s2 / 250.f;
  int bx = blockIdx.x*32, by = blockIdx.y*32;
  int tx = threadIdx.x, ty = threadIdx.y;
  for (int i = 0; i < 32; i += 8) {
    int r = by + ty + i, cc = bx + tx;
    float w = W[(size_t)r*NH + cc];
    t[ty + i][tx] = w;
    int8_t q1, q2, q3; quant3(w, s1, s2, s3, q1, q2, q3);
    size_t ix = (size_t)r*NH + cc;
    g_Wq1[ix] = q1; g_Wq2[ix] = q2; g_Wq3[ix] = q3;
  }
  __syncthreads();
  for (int i = 0; i < 32; i += 8) {
    float w = t[tx][ty + i];   // W[by+tx][bx+ty+i]
    int8_t q1, q2, q3; quant3(w, s1, s2, s3, q1, q2, q3);
    size_t ix = (size_t)(bx + ty + i)*NV + by + tx;
    g_Tq1[ix] = q1; g_Tq2[ix] = q2; g_Tq3[ix] = q3;
  }
}

__global__ void colsum_kernel(const float* __restrict__ W) {
  int h = blockIdx.x * blockDim.x + threadIdx.x;
  float s = 0.f;
  for (int v2 = 0; v2 < NV; v2++) s += W[(size_t)v2*NH + h];
  g_colsum[h] = s;
}
__global__ void copyv_kernel(const float* __restrict__ v_data) {
  int i = blockIdx.x * blockDim.x + threadIdx.x;
  float4 v = ((const float4*)v_data)[i];
  char4 o;
  o.x = (char)(v.x != 0.0f); o.y = (char)(v.y != 0.0f);
  o.z = (char)(v.z != 0.0f); o.w = (char)(v.w != 0.0f);
  ((char4*)g_v8)[i] = o;
}
__global__ void u0_kernel(uint32_t ka, uint32_t kb) {
  int i = blockIdx.x * blockDim.x + threadIdx.x;
  if (i == 0) g_acc = 0.0;
  if (i < BATCH) g_u[i] = (jax_uniform(ka, kb, (uint32_t)i) < 0.5f) ? 1.0f : 0.0f;
}

// ---- free energy ----
// USE_GV: v from g_v8 (model) else vparam (data). WSRC 0: vW from g_vwd ; 1: from g_a
template<bool USE_GV, int WSRC>
__global__ void fe_kernel(const float* __restrict__ vparam, double sign) {
  int row = blockIdx.x, tid = threadIdx.x, wrp = tid >> 5, lane = tid & 31;
  const float* br = g_bmod + (size_t)row*NV;
  const float* wr = (WSRC == 0 ? g_vwd : g_a) + (size_t)row*NH;
  const float* cr = g_cmod + (size_t)row*NH;
  float spn = 0, spf = 0, svb = 0, sb = 0;
  for (int j = tid; j < NV; j += 256) {
    float vv = USE_GV ? (float)g_v8[(size_t)row*NV + j] : vparam[(size_t)row*NV + j];
    float bbv = br[j];
    svb += vv*bbv; sb += bbv;
    float w = wr[j], cm = cr[j];
    spn += softplusf_(w + cm);
    spf += softplusf_(g_colsum[j] - w + cm);
  }
#pragma unroll
  for (int o = 16; o > 0; o >>= 1) {
    spn += __shfl_down_sync(0xffffffffu, spn, o);
    spf += __shfl_down_sync(0xffffffffu, spf, o);
    svb += __shfl_down_sync(0xffffffffu, svb, o);
    sb  += __shfl_down_sync(0xffffffffu, sb,  o);
  }
  __shared__ float red[4][8];
  if (lane == 0) { red[0][wrp] = spn; red[1][wrp] = spf; red[2][wrp] = svb; red[3][wrp] = sb; }
  __syncthreads();
  if (tid == 0) {
    float SPN=0, SPF=0, SVB=0, SB=0;
#pragma unroll
    for (int w = 0; w < 8; w++) { SPN += red[0][w]; SPF += red[1][w]; SVB += red[2][w]; SB += red[3][w]; }
    float a1 = SVB + SPN;            // -F_normal
    float a2 = (SB - SVB) + SPF;     // -F_flipped
    float m  = fmaxf(a1, a2);
    float lse = m + logf(expf(a1 - m) + expf(a2 - m));
    atomicAdd(&g_acc, sign * (double)(-lse));
  }
}

__global__ void final_kernel(float* out) { out[0] = (float)(g_acc / (double)BATCH); }

// ---- host ----
struct K2 { uint32_t a, b; };
static inline K2 tf_child(K2 k, uint32_t i) { K2 r; tf2x32(k.a, k.b, 0u, i, r.a, r.b); return r; }

extern "C" void kernel_launch(void* const* d_in, const int* in_sizes, int n_in,
                              void* d_out, int out_size) {
  (void)in_sizes; (void)n_in; (void)out_size;
  const float* v_data = (const float*)d_in[0];
  const float* cond   = (const float*)d_in[1];
  const float* W      = (const float*)d_in[2];
  const float* b      = (const float*)d_in[3];
  const float* c      = (const float*)d_in[4];
  const float* fc1w   = (const float*)d_in[5];
  const float* fc1b   = (const float*)d_in[6];
  const float* fc2w   = (const float*)d_in[7];
  const float* fc2b   = (const float*)d_in[8];

  K2 root = {0u, 42u};
  K2 k_u = tf_child(root, 0u), k_chain = tf_child(root, 1u);
  K2 kh[KSTEPS], kv[KSTEPS];
  for (int s = 0; s < KSTEPS; s++) {
    K2 sk = tf_child(k_chain, (uint32_t)s);
    kh[s] = tf_child(sk, 0u);
    kv[s] = tf_child(sk, 2u);
  }

  cudaFuncSetAttribute(gemm_i8<1, true , true >, cudaFuncAttributeMaxDynamicSharedMemorySize, SMQ_TOTAL);
  cudaFuncSetAttribute(gemm_i8<1, false, false>, cudaFuncAttributeMaxDynamicSharedMemorySize, SMQ_TOTAL);
  cudaFuncSetAttribute(gemm_i8<2, false, false>, cudaFuncAttributeMaxDynamicSharedMemorySize, SMQ_TOTAL);
  cudaFuncSetAttribute(gemm_i8<4, false, false>, cudaFuncAttributeMaxDynamicSharedMemorySize, SMQ_TOTAL);

  dim3 gg(NH / 128, BATCH / 128);   // (8, 128) = 1024 CTAs

  biases_kernel<<<BATCH / BT_ROWS, 256>>>(cond, b, c, fc1w, fc1b, fc2w, fc2b);
  maxabs_kernel<<<(NV * NH) / 256, 256>>>(W);
  splitq_kernel<<<dim3(32, 32), dim3(32, 8)>>>(W);
  colsum_kernel<<<NH / 256, 256>>>(W);
  copyv_kernel<<<(BATCH * NV / 4) / 256, 256>>>(v_data);
  u0_kernel<<<BATCH / 256, 256>>>(k_u.a, k_u.b);

  for (int s = 0; s < KSTEPS; s++) {
    if (s == 0) gemm_i8<1, true , true ><<<gg, 512, SMQ_TOTAL>>>(kh[s].a, kh[s].b);
    else        gemm_i8<1, false, false><<<gg, 512, SMQ_TOTAL>>>(kh[s].a, kh[s].b);
    gemm_i8<2, false, false><<<gg, 512, SMQ_TOTAL>>>(kv[s].a, kv[s].b);
  }
  fe_kernel<false, 0><<<BATCH, 256>>>(v_data, +1.0);
  gemm_i8<4, false, false><<<gg, 512, SMQ_TOTAL>>>(0u, 0u);   // vbn_9 @ W -> g_a
  fe_kernel<true, 1><<<BATCH, 256>>>(nullptr, -1.0);
  final_kernel<<<1, 1>>>((float*)d_out);
}

// round 14
// speedup vs baseline: 3.1960x; 3.1960x over previous
#include <cuda_runtime.h>
#include <cuda_bf16.h>
#include <cstdint>
#include <cmath>

#define BATCH 16384
#define NV 1024
#define NH 1024
#define HD 64
#define KSTEPS 10

__device__ float         g_bmod[(size_t)BATCH * NV];
__device__ float         g_cmod[(size_t)BATCH * NH];
__device__ float         g_a   [(size_t)BATCH * NV];   // vW of v_model (MODE 4 only)
__device__ float         g_vwd [(size_t)BATCH * NV];   // recovered v_data@W for FE-data
__device__ __nv_bfloat16 g_vb  [(size_t)BATCH * NV];   // v_data, then vbn chain state
__device__ __nv_bfloat16 g_hb  [(size_t)BATCH * NH];
__device__ float         g_u   [BATCH];                // u0 only (loss is u-invariant)
__device__ __nv_bfloat16 g_Whi[NV*NH], g_Wlo[NV*NH];   // [v][h] (k=h contiguous)
__device__ __nv_bfloat16 g_Thi[NV*NH], g_Tlo[NV*NH];   // [h][v] (k=v contiguous)
__device__ float         g_colsum[NH];
__device__ double        g_acc;

__host__ __device__ __forceinline__ void tf2x32(uint32_t k0, uint32_t k1,
                                                uint32_t x0, uint32_t x1,
                                                uint32_t& o0, uint32_t& o1) {
  uint32_t ks2 = k0 ^ k1 ^ 0x1BD11BDAu;
#define TF_R(r) { x0 += x1; x1 = (x1 << (r)) | (x1 >> (32 - (r))); x1 ^= x0; }
  x0 += k0; x1 += k1;
  TF_R(13) TF_R(15) TF_R(26) TF_R(6)   x0 += k1;  x1 += ks2 + 1u;
  TF_R(17) TF_R(29) TF_R(16) TF_R(24)  x0 += ks2; x1 += k0 + 2u;
  TF_R(13) TF_R(15) TF_R(26) TF_R(6)   x0 += k0;  x1 += k1 + 3u;
  TF_R(17) TF_R(29) TF_R(16) TF_R(24)  x0 += k1;  x1 += ks2 + 4u;
  TF_R(13) TF_R(15) TF_R(26) TF_R(6)   x0 += ks2; x1 += k0 + 5u;
#undef TF_R
  o0 = x0; o1 = x1;
}
__device__ __forceinline__ float jax_uniform(uint32_t ka, uint32_t kb, uint32_t idx) {
  uint32_t o0, o1; tf2x32(ka, kb, 0u, idx, o0, o1);
  return __uint_as_float(((o0 ^ o1) >> 9) | 0x3f800000u) - 1.0f;
}
__device__ __forceinline__ float sigmoidf_(float x)  { return 1.0f / (1.0f + expf(-x)); }
__device__ __forceinline__ float softplusf_(float x) { return fmaxf(x, 0.0f) + log1pf(expf(-fabsf(x))); }

__device__ __forceinline__ uint32_t smem_to_u32(const void* p) {
  uint32_t a;
  asm("{ .reg .u64 t; cvta.to.shared.u64 t, %1; cvt.u32.u64 %0, t; }" : "=r"(a) : "l"(p));
  return a;
}
__device__ __forceinline__ void sts128(uint32_t a, uint4 v) {
  asm volatile("st.shared.v4.b32 [%0], {%1,%2,%3,%4};" :: "r"(a), "r"(v.x), "r"(v.y), "r"(v.z), "r"(v.w) : "memory");
}
#define LDSM_X4(r0, r1, r2, r3, addr) \
  asm volatile("ldmatrix.sync.aligned.m8n8.x4.shared.b16 {%0,%1,%2,%3}, [%4];" \
    : "=r"(r0), "=r"(r1), "=r"(r2), "=r"(r3) : "r"(addr))

// ---------------- bf16 mma GEMM ----------------
// Tile 128x128, 16 k-blocks of 64, W = Whi + Wlo (2-way bf16 split), 2 CTAs/SM
// Single sync per k-block, ROUND-9-VALIDATED ordering: ALL smem writes
// (issueB, stsA) are issued strictly AFTER the top barrier, so the barrier of
// iteration k orders every iteration-(k-1) read before every iteration-k write.
// MODE 1: A=g_vb (FLIP: xor by u), B=T* -> sample h into g_hb (S0: recover vdata@W -> g_vwd)
// MODE 2: A=g_hb, B=W* -> sample vbn into g_vb (reads g_bmod)
// MODE 4: A=g_vb, B=T* -> write g_a (for FE-model)
#define NKB 16
#define ASTR 144                       // bytes per 64-elem row (72 bf16, padded)
#define TILE_B (128 * ASTR)            // 18432
#define SM_TOTAL (6 * TILE_B)          // 110592: A0,A1,Bhi0,Bhi1,Blo0,Blo1

template<int MODE, bool S0, bool FLIP>
__global__ void __launch_bounds__(256, 2) gemm_mma(uint32_t ka, uint32_t kb) {
  extern __shared__ char smem[];
  uint32_t sbase = smem_to_u32(smem);
  int tid = threadIdx.x, lane = tid & 31, wid = tid >> 5;
  int wm = wid & 1, wn = wid >> 1;             // warp grid 2(M) x 4(N)
  int gq = lane >> 2, tg = lane & 3;
  int bm = blockIdx.y * 128, bn = blockIdx.x * 128;

  const __nv_bfloat16* A  = (MODE == 2) ? g_hb : g_vb;
  const __nv_bfloat16* Bh = (MODE == 2) ? g_Whi : g_Thi;
  const __nv_bfloat16* Bl = (MODE == 2) ? g_Wlo : g_Tlo;

  int lrow[4]; uint32_t uxr[4];
#pragma unroll
  for (int q = 0; q < 4; q++) {
    lrow[q] = (tid >> 3) + 32 * q;
    uxr[q] = 0u;
    if (FLIP) uxr[q] = (g_u[bm + lrow[q]] == 0.0f) ? 0x3F803F80u : 0u;
  }
  int seg = tid & 7;

  uint4 aregs[4];
  auto ldgA = [&](int kbk) {
    int kin = kbk * 64;
#pragma unroll
    for (int q = 0; q < 4; q++) {
      uint4 v = *(const uint4*)(A + (((size_t)(bm + lrow[q])) << 10) + kin + seg * 8);
      if (FLIP) { v.x ^= uxr[q]; v.y ^= uxr[q]; v.z ^= uxr[q]; v.w ^= uxr[q]; }
      aregs[q] = v;
    }
  };
  auto stsA = [&](int buf) {
    uint32_t base = sbase + buf * TILE_B;
#pragma unroll
    for (int q = 0; q < 4; q++)
      sts128(base + lrow[q] * ASTR + seg * 16, aregs[q]);
  };
  auto issueB = [&](int kbk) {
    int kin = kbk * 64, buf = kbk & 1;
    uint32_t bh = sbase + (2 + buf) * TILE_B;
    uint32_t bl = sbase + (4 + buf) * TILE_B;
#pragma unroll
    for (int q = 0; q < 4; q++) {
      uint32_t soff = lrow[q] * ASTR + seg * 16;
      size_t goff = (((size_t)(bn + lrow[q])) << 10) + kin + seg * 8;
      asm volatile("cp.async.cg.shared.global [%0], [%1], 16;" :: "r"(bh + soff), "l"((const void*)(Bh + goff)) : "memory");
      asm volatile("cp.async.cg.shared.global [%0], [%1], 16;" :: "r"(bl + soff), "l"((const void*)(Bl + goff)) : "memory");
    }
    asm volatile("cp.async.commit_group;" ::: "memory");
  };

  float acc[4][4][4];
#pragma unroll
  for (int i = 0; i < 4; i++)
#pragma unroll
    for (int j = 0; j < 4; j++)
#pragma unroll
      for (int q = 0; q < 4; q++) acc[i][j][q] = 0.f;

  // prologue
  ldgA(0); stsA(0);
  issueB(0);
  ldgA(1);

  uint32_t a_l15 = (uint32_t)(lane & 15), a_hi16 = (uint32_t)((lane >> 4) << 4);
  uint32_t b_row = (uint32_t)((lane & 7) + ((lane >> 4) << 3));
  uint32_t b_k16 = (uint32_t)(((lane >> 3) & 1) << 4);

  for (int kbk = 0; kbk < NKB; kbk++) {
    asm volatile("cp.async.wait_group 0;" ::: "memory");
    __syncthreads();                      // single sync; ALL writes below are after it
    if (kbk + 1 < NKB) { issueB(kbk + 1); stsA((kbk + 1) & 1); }
    if (kbk + 2 < NKB) ldgA(kbk + 2);

    uint32_t Ab  = sbase + (kbk & 1) * TILE_B;
    uint32_t Bhb = sbase + (2 + (kbk & 1)) * TILE_B;
    uint32_t Blb = sbase + (4 + (kbk & 1)) * TILE_B;
#pragma unroll
    for (int ks = 0; ks < 4; ks++) {
      uint32_t afr[4][4];
#pragma unroll
      for (int i = 0; i < 4; i++) {
        uint32_t addr = Ab + (uint32_t)(wm * 64 + i * 16) * ASTR + a_l15 * ASTR + (uint32_t)(ks * 32) + a_hi16;
        LDSM_X4(afr[i][0], afr[i][1], afr[i][2], afr[i][3], addr);
      }
      uint32_t bhf[4][2], blf[4][2];
#pragma unroll
      for (int jp = 0; jp < 2; jp++) {
        uint32_t rowoff = ((uint32_t)(wn * 32 + jp * 16) + b_row) * ASTR + (uint32_t)(ks * 32) + b_k16;
        LDSM_X4(bhf[2*jp][0], bhf[2*jp][1], bhf[2*jp+1][0], bhf[2*jp+1][1], Bhb + rowoff);
        LDSM_X4(blf[2*jp][0], blf[2*jp][1], blf[2*jp+1][0], blf[2*jp+1][1], Blb + rowoff);
      }
#pragma unroll
      for (int i = 0; i < 4; i++)
#pragma unroll
        for (int j = 0; j < 4; j++)
          asm volatile("mma.sync.aligned.m16n8k16.row.col.f32.bf16.bf16.f32 "
            "{%0,%1,%2,%3}, {%4,%5,%6,%7}, {%8,%9}, {%0,%1,%2,%3};"
            : "+f"(acc[i][j][0]), "+f"(acc[i][j][1]), "+f"(acc[i][j][2]), "+f"(acc[i][j][3])
            : "r"(afr[i][0]), "r"(afr[i][1]), "r"(afr[i][2]), "r"(afr[i][3]),
              "r"(bhf[j][0]), "r"(bhf[j][1]));
#pragma unroll
      for (int i = 0; i < 4; i++)
#pragma unroll
        for (int j = 0; j < 4; j++)
          asm volatile("mma.sync.aligned.m16n8k16.row.col.f32.bf16.bf16.f32 "
            "{%0,%1,%2,%3}, {%4,%5,%6,%7}, {%8,%9}, {%0,%1,%2,%3};"
            : "+f"(acc[i][j][0]), "+f"(acc[i][j][1]), "+f"(acc[i][j][2]), "+f"(acc[i][j][3])
            : "r"(afr[i][0]), "r"(afr[i][1]), "r"(afr[i][2]), "r"(afr[i][3]),
              "r"(blf[j][0]), "r"(blf[j][1]));
    }
  }

  // epilogue
#pragma unroll
  for (int i = 0; i < 4; i++) {
    int row0 = bm + wm * 64 + i * 16 + gq;
#pragma unroll
    for (int j = 0; j < 4; j++) {
      int col = bn + wn * 32 + j * 8 + tg * 2;
#pragma unroll
      for (int half = 0; half < 2; half++) {
        int r = row0 + half * 8;
        uint32_t idx = ((uint32_t)r << 10) | (uint32_t)col;
        float v0 = acc[i][j][half * 2], v1 = acc[i][j][half * 2 + 1];
        if (MODE == 1) {
          if (S0) {   // recover vdata@W: u=1 -> D ; u=0 -> colsum - D
            float uu = g_u[r];
            float w0 = (uu != 0.0f) ? v0 : g_colsum[col]     - v0;
            float w1 = (uu != 0.0f) ? v1 : g_colsum[col + 1] - v1;
            *(float2*)(g_vwd + idx) = make_float2(w0, w1);
          }
          float2 cm = *(const float2*)(g_cmod + idx);
          float p0 = sigmoidf_(v0 + cm.x), p1 = sigmoidf_(v1 + cm.y);
          float u0 = jax_uniform(ka, kb, idx), u1 = jax_uniform(ka, kb, idx + 1);
          __nv_bfloat162 hv;
          hv.x = __float2bfloat16((u0 < p0) ? 1.0f : 0.0f);
          hv.y = __float2bfloat16((u1 < p1) ? 1.0f : 0.0f);
          *(__nv_bfloat162*)(g_hb + idx) = hv;
        } else if (MODE == 2) {
          // vbn = Bernoulli(sigmoid(a + b_mod)); u-flip cancels in next step, loss u-invariant
          float2 bm2 = *(const float2*)(g_bmod + idx);
          float p0 = sigmoidf_(v0 + bm2.x), p1 = sigmoidf_(v1 + bm2.y);
          float u0 = jax_uniform(ka, kb, idx), u1 = jax_uniform(ka, kb, idx + 1);
          __nv_bfloat162 vv;
          vv.x = __float2bfloat16((u0 < p0) ? 1.0f : 0.0f);
          vv.y = __float2bfloat16((u1 < p1) ? 1.0f : 0.0f);
          *(__nv_bfloat162*)(g_vb + idx) = vv;
        } else {
          *(float2*)(g_a + idx) = make_float2(v0, v1);
        }
      }
    }
  }
}

// ---- hypernetwork biases ----
#define BT_ROWS 16
__global__ void biases_kernel(const float* __restrict__ cond, const float* __restrict__ b,
                              const float* __restrict__ c, const float* __restrict__ fc1w,
                              const float* __restrict__ fc1b, const float* __restrict__ fc2w,
                              const float* __restrict__ fc2b) {
  __shared__ float xs[BT_ROWS][HD];
  int r0 = blockIdx.x * BT_ROWS, tid = threadIdx.x;
  for (int t = tid; t < BT_ROWS * HD; t += blockDim.x) {
    int r = t / HD, d = t % HD;
    xs[r][d] = tanhf(cond[r0 + r] * fc1w[d] + fc1b[d]);
  }
  __syncthreads();
  for (int j = tid; j < NV + NH; j += blockDim.x) {
    int gw, bw;
    if (j < NV) { gw = j; bw = NV + j; } else { gw = 2*NV + (j-NV); bw = 2*NV + NH + (j-NV); }
    const float* wg = fc2w + (size_t)gw * HD;
    const float* wb = fc2w + (size_t)bw * HD;
    float accG[BT_ROWS], accB[BT_ROWS];
#pragma unroll
    for (int r = 0; r < BT_ROWS; r++) { accG[r] = 0.f; accB[r] = 0.f; }
    for (int d = 0; d < HD; d++) {
      float g = wg[d], bb = wb[d];
#pragma unroll
      for (int r = 0; r < BT_ROWS; r++) { float x = xs[r][d]; accG[r] += g*x; accB[r] += bb*x; }
    }
    float gb = fc2b[gw], bbia = fc2b[bw];
    if (j < NV) {
      float bj = b[j];
      for (int r = 0; r < BT_ROWS; r++)
        g_bmod[(size_t)(r0 + r)*NV + j] = (1.0f + accG[r] + gb)*bj + (accB[r] + bbia);
    } else {
      int hh = j - NV; float ch = c[hh];
      for (int r = 0; r < BT_ROWS; r++)
        g_cmod[(size_t)(r0 + r)*NH + hh] = (1.0f + accG[r] + gb)*ch + (accB[r] + bbia);
    }
  }
}

// ---- W 2-way split, both layouts ----
__device__ __forceinline__ void split2(float w, __nv_bfloat16& hi, __nv_bfloat16& lo) {
  hi = __float2bfloat16(w);
  lo = __float2bfloat16(w - __bfloat162float(hi));
}
__global__ void splitT_kernel(const float* __restrict__ W) {
  __shared__ float t[32][33];
  int bx = blockIdx.x*32, by = blockIdx.y*32;
  int tx = threadIdx.x, ty = threadIdx.y;
  for (int i = 0; i < 32; i += 8) {
    int r = by + ty + i, cc = bx + tx;
    float w = W[(size_t)r*NH + cc];
    t[ty + i][tx] = w;
    __nv_bfloat16 hi, lo; split2(w, hi, lo);
    size_t ix = (size_t)r*NH + cc;
    g_Whi[ix] = hi; g_Wlo[ix] = lo;
  }
  __syncthreads();
  for (int i = 0; i < 32; i += 8) {
    float w = t[tx][ty + i];
    __nv_bfloat16 hi, lo; split2(w, hi, lo);
    size_t ix = (size_t)(bx + ty + i)*NV + by + tx;
    g_Thi[ix] = hi; g_Tlo[ix] = lo;
  }
}

__global__ void colsum_kernel(const float* __restrict__ W) {
  int h = blockIdx.x * blockDim.x + threadIdx.x;
  float s = 0.f;
  for (int v2 = 0; v2 < NV; v2++) s += W[(size_t)v2*NH + h];
  g_colsum[h] = s;
}
__global__ void copyv_kernel(const float* __restrict__ v_data) {
  int i = blockIdx.x * blockDim.x + threadIdx.x;
  float4 v = ((const float4*)v_data)[i];
  ushort4 o;
  o.x = __bfloat16_as_ushort(__float2bfloat16(v.x));
  o.y = __bfloat16_as_ushort(__float2bfloat16(v.y));
  o.z = __bfloat16_as_ushort(__float2bfloat16(v.z));
  o.w = __bfloat16_as_ushort(__float2bfloat16(v.w));
  ((ushort4*)g_vb)[i] = o;
}
__global__ void u0_kernel(uint32_t ka, uint32_t kb) {
  int i = blockIdx.x * blockDim.x + threadIdx.x;
  if (i == 0) g_acc = 0.0;
  if (i < BATCH) g_u[i] = (jax_uniform(ka, kb, (uint32_t)i) < 0.5f) ? 1.0f : 0.0f;
}

// ---- free energy ----
template<bool USE_GV, int WSRC>
__global__ void fe_kernel(const float* __restrict__ vparam, double sign) {
  int row = blockIdx.x, tid = threadIdx.x, wrp = tid >> 5, lane = tid & 31;
  const float* br = g_bmod + (size_t)row*NV;
  const float* wr = (WSRC == 0 ? g_vwd : g_a) + (size_t)row*NH;
  const float* cr = g_cmod + (size_t)row*NH;
  float spn = 0, spf = 0, svb = 0, sb = 0;
  for (int j = tid; j < NV; j += 256) {
    float vv = USE_GV ? __bfloat162float(g_vb[(size_t)row*NV + j]) : vparam[(size_t)row*NV + j];
    float bbv = br[j];
    svb += vv*bbv; sb += bbv;
    float w = wr[j], cm = cr[j];
    spn += softplusf_(w + cm);
    spf += softplusf_(g_colsum[j] - w + cm);
  }
#pragma unroll
  for (int o = 16; o > 0; o >>= 1) {
    spn += __shfl_down_sync(0xffffffffu, spn, o);
    spf += __shfl_down_sync(0xffffffffu, spf, o);
    svb += __shfl_down_sync(0xffffffffu, svb, o);
    sb  += __shfl_down_sync(0xffffffffu, sb,  o);
  }
  __shared__ float red[4][8];
  if (lane == 0) { red[0][wrp] = spn; red[1][wrp] = spf; red[2][wrp] = svb; red[3][wrp] = sb; }
  __syncthreads();
  if (tid == 0) {
    float SPN=0, SPF=0, SVB=0, SB=0;
#pragma unroll
    for (int w = 0; w < 8; w++) { SPN += red[0][w]; SPF += red[1][w]; SVB += red[2][w]; SB += red[3][w]; }
    float a1 = SVB + SPN;            // -F_normal
    float a2 = (SB - SVB) + SPF;     // -F_flipped
    float m  = fmaxf(a1, a2);
    float lse = m + logf(expf(a1 - m) + expf(a2 - m));
    atomicAdd(&g_acc, sign * (double)(-lse));
  }
}

__global__ void final_kernel(float* out) { out[0] = (float)(g_acc / (double)BATCH); }

// ---- host ----
struct K2 { uint32_t a, b; };
static inline K2 tf_child(K2 k, uint32_t i) { K2 r; tf2x32(k.a, k.b, 0u, i, r.a, r.b); return r; }

extern "C" void kernel_launch(void* const* d_in, const int* in_sizes, int n_in,
                              void* d_out, int out_size) {
  (void)in_sizes; (void)n_in; (void)out_size;
  const float* v_data = (const float*)d_in[0];
  const float* cond   = (const float*)d_in[1];
  const float* W      = (const float*)d_in[2];
  const float* b      = (const float*)d_in[3];
  const float* c      = (const float*)d_in[4];
  const float* fc1w   = (const float*)d_in[5];
  const float* fc1b   = (const float*)d_in[6];
  const float* fc2w   = (const float*)d_in[7];
  const float* fc2b   = (const float*)d_in[8];

  K2 root = {0u, 42u};
  K2 k_u = tf_child(root, 0u), k_chain = tf_child(root, 1u);
  K2 kh[KSTEPS], kv[KSTEPS];
  for (int s = 0; s < KSTEPS; s++) {
    K2 sk = tf_child(k_chain, (uint32_t)s);
    kh[s] = tf_child(sk, 0u);
    kv[s] = tf_child(sk, 2u);   // ku (index 1) unused: loss is u-invariant
  }

  cudaFuncSetAttribute(gemm_mma<1, true , true >, cudaFuncAttributeMaxDynamicSharedMemorySize, SM_TOTAL);
  cudaFuncSetAttribute(gemm_mma<1, false, false>, cudaFuncAttributeMaxDynamicSharedMemorySize, SM_TOTAL);
  cudaFuncSetAttribute(gemm_mma<2, false, false>, cudaFuncAttributeMaxDynamicSharedMemorySize, SM_TOTAL);
  cudaFuncSetAttribute(gemm_mma<4, false, false>, cudaFuncAttributeMaxDynamicSharedMemorySize, SM_TOTAL);

  dim3 gg(NH / 128, BATCH / 128);   // (8, 128) = 1024 CTAs

  biases_kernel<<<BATCH / BT_ROWS, 256>>>(cond, b, c, fc1w, fc1b, fc2w, fc2b);
  splitT_kernel<<<dim3(32, 32), dim3(32, 8)>>>(W);
  colsum_kernel<<<NH / 256, 256>>>(W);
  copyv_kernel<<<(BATCH * NV / 4) / 256, 256>>>(v_data);
  u0_kernel<<<BATCH / 256, 256>>>(k_u.a, k_u.b);

  for (int s = 0; s < KSTEPS; s++) {
    if (s == 0) gemm_mma<1, true , true ><<<gg, 256, SM_TOTAL>>>(kh[s].a, kh[s].b);
    else        gemm_mma<1, false, false><<<gg, 256, SM_TOTAL>>>(kh[s].a, kh[s].b);
    gemm_mma<2, false, false><<<gg, 256, SM_TOTAL>>>(kv[s].a, kv[s].b);
  }
  fe_kernel<false, 0><<<BATCH, 256>>>(v_data, +1.0);
  gemm_mma<4, false, false><<<gg, 256, SM_TOTAL>>>(0u, 0u);   // vbn_9 @ W -> g_a
  fe_kernel<true, 1><<<BATCH, 256>>>(nullptr, -1.0);
  final_kernel<<<1, 1>>>((float*)d_out);
}

// round 15
// speedup vs baseline: 3.5521x; 1.1114x over previous
#include <cuda_runtime.h>
#include <cuda_bf16.h>
#include <cstdint>
#include <cmath>

#define BATCH 16384
#define NV 1024
#define NH 1024
#define HD 64
#define KSTEPS 10
#define NHALF 2
#define HROWS (BATCH / NHALF)          // 8192 rows per stream-half

__device__ float         g_bmod[(size_t)BATCH * NV];
__device__ float         g_cmod[(size_t)BATCH * NH];
__device__ float         g_a   [(size_t)BATCH * NV];   // vW of v_model (MODE 4 only)
__device__ float         g_vwd [(size_t)BATCH * NV];   // recovered v_data@W for FE-data
__device__ __nv_bfloat16 g_vb  [(size_t)BATCH * NV];   // v_data, then vbn chain state
__device__ __nv_bfloat16 g_hb  [(size_t)BATCH * NH];
__device__ float         g_u   [BATCH];                // u0 only (loss is u-invariant)
__device__ __nv_bfloat16 g_Whi[NV*NH], g_Wlo[NV*NH];   // [v][h] (k=h contiguous)
__device__ __nv_bfloat16 g_Thi[NV*NH], g_Tlo[NV*NH];   // [h][v] (k=v contiguous)
__device__ float         g_colsum[NH];
__device__ double        g_acc;

__host__ __device__ __forceinline__ void tf2x32(uint32_t k0, uint32_t k1,
                                                uint32_t x0, uint32_t x1,
                                                uint32_t& o0, uint32_t& o1) {
  uint32_t ks2 = k0 ^ k1 ^ 0x1BD11BDAu;
#define TF_R(r) { x0 += x1; x1 = (x1 << (r)) | (x1 >> (32 - (r))); x1 ^= x0; }
  x0 += k0; x1 += k1;
  TF_R(13) TF_R(15) TF_R(26) TF_R(6)   x0 += k1;  x1 += ks2 + 1u;
  TF_R(17) TF_R(29) TF_R(16) TF_R(24)  x0 += ks2; x1 += k0 + 2u;
  TF_R(13) TF_R(15) TF_R(26) TF_R(6)   x0 += k0;  x1 += k1 + 3u;
  TF_R(17) TF_R(29) TF_R(16) TF_R(24)  x0 += k1;  x1 += ks2 + 4u;
  TF_R(13) TF_R(15) TF_R(26) TF_R(6)   x0 += ks2; x1 += k0 + 5u;
#undef TF_R
  o0 = x0; o1 = x1;
}
__device__ __forceinline__ float jax_uniform(uint32_t ka, uint32_t kb, uint32_t idx) {
  uint32_t o0, o1; tf2x32(ka, kb, 0u, idx, o0, o1);
  return __uint_as_float(((o0 ^ o1) >> 9) | 0x3f800000u) - 1.0f;
}
__device__ __forceinline__ float sigmoidf_(float x)  { return 1.0f / (1.0f + expf(-x)); }
__device__ __forceinline__ float softplusf_(float x) { return fmaxf(x, 0.0f) + log1pf(expf(-fabsf(x))); }

__device__ __forceinline__ uint32_t smem_to_u32(const void* p) {
  uint32_t a;
  asm("{ .reg .u64 t; cvta.to.shared.u64 t, %1; cvt.u32.u64 %0, t; }" : "=r"(a) : "l"(p));
  return a;
}
__device__ __forceinline__ void sts128(uint32_t a, uint4 v) {
  asm volatile("st.shared.v4.b32 [%0], {%1,%2,%3,%4};" :: "r"(a), "r"(v.x), "r"(v.y), "r"(v.z), "r"(v.w) : "memory");
}
#define LDSM_X4(r0, r1, r2, r3, addr) \
  asm volatile("ldmatrix.sync.aligned.m8n8.x4.shared.b16 {%0,%1,%2,%3}, [%4];" \
    : "=r"(r0), "=r"(r1), "=r"(r2), "=r"(r3) : "r"(addr))

// ---------------- bf16 mma GEMM ----------------
// Tile 128x128, 16 k-blocks of 64, W = Whi + Wlo (2-way bf16 split), 2 CTAs/SM
// Single sync per k-block (round-9-validated ordering: all smem writes after it).
// ybase: M-tile offset in units of 128 rows (stream-half partitioning).
// MODE 1: A=g_vb (FLIP: xor by u), B=T* -> sample h into g_hb (S0: recover vdata@W -> g_vwd)
// MODE 2: A=g_hb, B=W* -> sample vbn into g_vb (reads g_bmod)
// MODE 4: A=g_vb, B=T* -> write g_a (for FE-model)
#define NKB 16
#define ASTR 144                       // bytes per 64-elem row (72 bf16, padded)
#define TILE_B (128 * ASTR)            // 18432
#define SM_TOTAL (6 * TILE_B)          // 110592: A0,A1,Bhi0,Bhi1,Blo0,Blo1

template<int MODE, bool S0, bool FLIP>
__global__ void __launch_bounds__(256, 2) gemm_mma(uint32_t ka, uint32_t kb, int ybase) {
  extern __shared__ char smem[];
  uint32_t sbase = smem_to_u32(smem);
  int tid = threadIdx.x, lane = tid & 31, wid = tid >> 5;
  int wm = wid & 1, wn = wid >> 1;             // warp grid 2(M) x 4(N)
  int gq = lane >> 2, tg = lane & 3;
  int bm = (blockIdx.y + ybase) * 128, bn = blockIdx.x * 128;

  const __nv_bfloat16* A  = (MODE == 2) ? g_hb : g_vb;
  const __nv_bfloat16* Bh = (MODE == 2) ? g_Whi : g_Thi;
  const __nv_bfloat16* Bl = (MODE == 2) ? g_Wlo : g_Tlo;

  int lrow[4]; uint32_t uxr[4];
#pragma unroll
  for (int q = 0; q < 4; q++) {
    lrow[q] = (tid >> 3) + 32 * q;
    uxr[q] = 0u;
    if (FLIP) uxr[q] = (g_u[bm + lrow[q]] == 0.0f) ? 0x3F803F80u : 0u;
  }
  int seg = tid & 7;

  uint4 aregs[4];
  auto ldgA = [&](int kbk) {
    int kin = kbk * 64;
#pragma unroll
    for (int q = 0; q < 4; q++) {
      uint4 v = *(const uint4*)(A + (((size_t)(bm + lrow[q])) << 10) + kin + seg * 8);
      if (FLIP) { v.x ^= uxr[q]; v.y ^= uxr[q]; v.z ^= uxr[q]; v.w ^= uxr[q]; }
      aregs[q] = v;
    }
  };
  auto stsA = [&](int buf) {
    uint32_t base = sbase + buf * TILE_B;
#pragma unroll
    for (int q = 0; q < 4; q++)
      sts128(base + lrow[q] * ASTR + seg * 16, aregs[q]);
  };
  auto issueB = [&](int kbk) {
    int kin = kbk * 64, buf = kbk & 1;
    uint32_t bh = sbase + (2 + buf) * TILE_B;
    uint32_t bl = sbase + (4 + buf) * TILE_B;
#pragma unroll
    for (int q = 0; q < 4; q++) {
      uint32_t soff = lrow[q] * ASTR + seg * 16;
      size_t goff = (((size_t)(bn + lrow[q])) << 10) + kin + seg * 8;
      asm volatile("cp.async.cg.shared.global [%0], [%1], 16;" :: "r"(bh + soff), "l"((const void*)(Bh + goff)) : "memory");
      asm volatile("cp.async.cg.shared.global [%0], [%1], 16;" :: "r"(bl + soff), "l"((const void*)(Bl + goff)) : "memory");
    }
    asm volatile("cp.async.commit_group;" ::: "memory");
  };

  float acc[4][4][4];
#pragma unroll
  for (int i = 0; i < 4; i++)
#pragma unroll
    for (int j = 0; j < 4; j++)
#pragma unroll
      for (int q = 0; q < 4; q++) acc[i][j][q] = 0.f;

  // prologue
  ldgA(0); stsA(0);
  issueB(0);
  ldgA(1);

  uint32_t a_l15 = (uint32_t)(lane & 15), a_hi16 = (uint32_t)((lane >> 4) << 4);
  uint32_t b_row = (uint32_t)((lane & 7) + ((lane >> 4) << 3));
  uint32_t b_k16 = (uint32_t)(((lane >> 3) & 1) << 4);

  for (int kbk = 0; kbk < NKB; kbk++) {
    asm volatile("cp.async.wait_group 0;" ::: "memory");
    __syncthreads();                      // single sync; ALL writes below are after it
    if (kbk + 1 < NKB) { issueB(kbk + 1); stsA((kbk + 1) & 1); }
    if (kbk + 2 < NKB) ldgA(kbk + 2);

    uint32_t Ab  = sbase + (kbk & 1) * TILE_B;
    uint32_t Bhb = sbase + (2 + (kbk & 1)) * TILE_B;
    uint32_t Blb = sbase + (4 + (kbk & 1)) * TILE_B;
#pragma unroll
    for (int ks = 0; ks < 4; ks++) {
      uint32_t afr[4][4];
#pragma unroll
      for (int i = 0; i < 4; i++) {
        uint32_t addr = Ab + (uint32_t)(wm * 64 + i * 16) * ASTR + a_l15 * ASTR + (uint32_t)(ks * 32) + a_hi16;
        LDSM_X4(afr[i][0], afr[i][1], afr[i][2], afr[i][3], addr);
      }
      uint32_t bhf[4][2], blf[4][2];
#pragma unroll
      for (int jp = 0; jp < 2; jp++) {
        uint32_t rowoff = ((uint32_t)(wn * 32 + jp * 16) + b_row) * ASTR + (uint32_t)(ks * 32) + b_k16;
        LDSM_X4(bhf[2*jp][0], bhf[2*jp][1], bhf[2*jp+1][0], bhf[2*jp+1][1], Bhb + rowoff);
        LDSM_X4(blf[2*jp][0], blf[2*jp][1], blf[2*jp+1][0], blf[2*jp+1][1], Blb + rowoff);
      }
#pragma unroll
      for (int i = 0; i < 4; i++)
#pragma unroll
        for (int j = 0; j < 4; j++)
          asm volatile("mma.sync.aligned.m16n8k16.row.col.f32.bf16.bf16.f32 "
            "{%0,%1,%2,%3}, {%4,%5,%6,%7}, {%8,%9}, {%0,%1,%2,%3};"
            : "+f"(acc[i][j][0]), "+f"(acc[i][j][1]), "+f"(acc[i][j][2]), "+f"(acc[i][j][3])
            : "r"(afr[i][0]), "r"(afr[i][1]), "r"(afr[i][2]), "r"(afr[i][3]),
              "r"(bhf[j][0]), "r"(bhf[j][1]));
#pragma unroll
      for (int i = 0; i < 4; i++)
#pragma unroll
        for (int j = 0; j < 4; j++)
          asm volatile("mma.sync.aligned.m16n8k16.row.col.f32.bf16.bf16.f32 "
            "{%0,%1,%2,%3}, {%4,%5,%6,%7}, {%8,%9}, {%0,%1,%2,%3};"
            : "+f"(acc[i][j][0]), "+f"(acc[i][j][1]), "+f"(acc[i][j][2]), "+f"(acc[i][j][3])
            : "r"(afr[i][0]), "r"(afr[i][1]), "r"(afr[i][2]), "r"(afr[i][3]),
              "r"(blf[j][0]), "r"(blf[j][1]));
    }
  }

  // epilogue
#pragma unroll
  for (int i = 0; i < 4; i++) {
    int row0 = bm + wm * 64 + i * 16 + gq;
#pragma unroll
    for (int j = 0; j < 4; j++) {
      int col = bn + wn * 32 + j * 8 + tg * 2;
#pragma unroll
      for (int half = 0; half < 2; half++) {
        int r = row0 + half * 8;
        uint32_t idx = ((uint32_t)r << 10) | (uint32_t)col;
        float v0 = acc[i][j][half * 2], v1 = acc[i][j][half * 2 + 1];
        if (MODE == 1) {
          if (S0) {   // recover vdata@W: u=1 -> D ; u=0 -> colsum - D
            float uu = g_u[r];
            float w0 = (uu != 0.0f) ? v0 : g_colsum[col]     - v0;
            float w1 = (uu != 0.0f) ? v1 : g_colsum[col + 1] - v1;
            *(float2*)(g_vwd + idx) = make_float2(w0, w1);
          }
          float2 cm = *(const float2*)(g_cmod + idx);
          float p0 = sigmoidf_(v0 + cm.x), p1 = sigmoidf_(v1 + cm.y);
          float u0 = jax_uniform(ka, kb, idx), u1 = jax_uniform(ka, kb, idx + 1);
          __nv_bfloat162 hv;
          hv.x = __float2bfloat16((u0 < p0) ? 1.0f : 0.0f);
          hv.y = __float2bfloat16((u1 < p1) ? 1.0f : 0.0f);
          *(__nv_bfloat162*)(g_hb + idx) = hv;
        } else if (MODE == 2) {
          // vbn = Bernoulli(sigmoid(a + b_mod)); u-flip cancels in next step, loss u-invariant
          float2 bm2 = *(const float2*)(g_bmod + idx);
          float p0 = sigmoidf_(v0 + bm2.x), p1 = sigmoidf_(v1 + bm2.y);
          float u0 = jax_uniform(ka, kb, idx), u1 = jax_uniform(ka, kb, idx + 1);
          __nv_bfloat162 vv;
          vv.x = __float2bfloat16((u0 < p0) ? 1.0f : 0.0f);
          vv.y = __float2bfloat16((u1 < p1) ? 1.0f : 0.0f);
          *(__nv_bfloat162*)(g_vb + idx) = vv;
        } else {
          *(float2*)(g_a + idx) = make_float2(v0, v1);
        }
      }
    }
  }
}

// ---- hypernetwork biases ----
#define BT_ROWS 16
__global__ void biases_kernel(const float* __restrict__ cond, const float* __restrict__ b,
                              const float* __restrict__ c, const float* __restrict__ fc1w,
                              const float* __restrict__ fc1b, const float* __restrict__ fc2w,
                              const float* __restrict__ fc2b) {
  __shared__ float xs[BT_ROWS][HD];
  int r0 = blockIdx.x * BT_ROWS, tid = threadIdx.x;
  for (int t = tid; t < BT_ROWS * HD; t += blockDim.x) {
    int r = t / HD, d = t % HD;
    xs[r][d] = tanhf(cond[r0 + r] * fc1w[d] + fc1b[d]);
  }
  __syncthreads();
  for (int j = tid; j < NV + NH; j += blockDim.x) {
    int gw, bw;
    if (j < NV) { gw = j; bw = NV + j; } else { gw = 2*NV + (j-NV); bw = 2*NV + NH + (j-NV); }
    const float* wg = fc2w + (size_t)gw * HD;
    const float* wb = fc2w + (size_t)bw * HD;
    float accG[BT_ROWS], accB[BT_ROWS];
#pragma unroll
    for (int r = 0; r < BT_ROWS; r++) { accG[r] = 0.f; accB[r] = 0.f; }
    for (int d = 0; d < HD; d++) {
      float g = wg[d], bb = wb[d];
#pragma unroll
      for (int r = 0; r < BT_ROWS; r++) { float x = xs[r][d]; accG[r] += g*x; accB[r] += bb*x; }
    }
    float gb = fc2b[gw], bbia = fc2b[bw];
    if (j < NV) {
      float bj = b[j];
      for (int r = 0; r < BT_ROWS; r++)
        g_bmod[(size_t)(r0 + r)*NV + j] = (1.0f + accG[r] + gb)*bj + (accB[r] + bbia);
    } else {
      int hh = j - NV; float ch = c[hh];
      for (int r = 0; r < BT_ROWS; r++)
        g_cmod[(size_t)(r0 + r)*NH + hh] = (1.0f + accG[r] + gb)*ch + (accB[r] + bbia);
    }
  }
}

// ---- W 2-way split, both layouts ----
__device__ __forceinline__ void split2(float w, __nv_bfloat16& hi, __nv_bfloat16& lo) {
  hi = __float2bfloat16(w);
  lo = __float2bfloat16(w - __bfloat162float(hi));
}
__global__ void splitT_kernel(const float* __restrict__ W) {
  __shared__ float t[32][33];
  int bx = blockIdx.x*32, by = blockIdx.y*32;
  int tx = threadIdx.x, ty = threadIdx.y;
  for (int i = 0; i < 32; i += 8) {
    int r = by + ty + i, cc = bx + tx;
    float w = W[(size_t)r*NH + cc];
    t[ty + i][tx] = w;
    __nv_bfloat16 hi, lo; split2(w, hi, lo);
    size_t ix = (size_t)r*NH + cc;
    g_Whi[ix] = hi; g_Wlo[ix] = lo;
  }
  __syncthreads();
  for (int i = 0; i < 32; i += 8) {
    float w = t[tx][ty + i];
    __nv_bfloat16 hi, lo; split2(w, hi, lo);
    size_t ix = (size_t)(bx + ty + i)*NV + by + tx;
    g_Thi[ix] = hi; g_Tlo[ix] = lo;
  }
}

__global__ void colsum_kernel(const float* __restrict__ W) {
  int h = blockIdx.x * blockDim.x + threadIdx.x;
  float s = 0.f;
  for (int v2 = 0; v2 < NV; v2++) s += W[(size_t)v2*NH + h];
  g_colsum[h] = s;
}
__global__ void copyv_kernel(const float* __restrict__ v_data) {
  int i = blockIdx.x * blockDim.x + threadIdx.x;
  float4 v = ((const float4*)v_data)[i];
  ushort4 o;
  o.x = __bfloat16_as_ushort(__float2bfloat16(v.x));
  o.y = __bfloat16_as_ushort(__float2bfloat16(v.y));
  o.z = __bfloat16_as_ushort(__float2bfloat16(v.z));
  o.w = __bfloat16_as_ushort(__float2bfloat16(v.w));
  ((ushort4*)g_vb)[i] = o;
}
__global__ void u0_kernel(uint32_t ka, uint32_t kb) {
  int i = blockIdx.x * blockDim.x + threadIdx.x;
  if (i == 0) g_acc = 0.0;
  if (i < BATCH) g_u[i] = (jax_uniform(ka, kb, (uint32_t)i) < 0.5f) ? 1.0f : 0.0f;
}

// ---- free energy (rbase: row offset for stream-half) ----
template<bool USE_GV, int WSRC>
__global__ void fe_kernel(const float* __restrict__ vparam, double sign, int rbase) {
  int row = blockIdx.x + rbase, tid = threadIdx.x, wrp = tid >> 5, lane = tid & 31;
  const float* br = g_bmod + (size_t)row*NV;
  const float* wr = (WSRC == 0 ? g_vwd : g_a) + (size_t)row*NH;
  const float* cr = g_cmod + (size_t)row*NH;
  float spn = 0, spf = 0, svb = 0, sb = 0;
  for (int j = tid; j < NV; j += 256) {
    float vv = USE_GV ? __bfloat162float(g_vb[(size_t)row*NV + j]) : vparam[(size_t)row*NV + j];
    float bbv = br[j];
    svb += vv*bbv; sb += bbv;
    float w = wr[j], cm = cr[j];
    spn += softplusf_(w + cm);
    spf += softplusf_(g_colsum[j] - w + cm);
  }
#pragma unroll
  for (int o = 16; o > 0; o >>= 1) {
    spn += __shfl_down_sync(0xffffffffu, spn, o);
    spf += __shfl_down_sync(0xffffffffu, spf, o);
    svb += __shfl_down_sync(0xffffffffu, svb, o);
    sb  += __shfl_down_sync(0xffffffffu, sb,  o);
  }
  __shared__ float red[4][8];
  if (lane == 0) { red[0][wrp] = spn; red[1][wrp] = spf; red[2][wrp] = svb; red[3][wrp] = sb; }
  __syncthreads();
  if (tid == 0) {
    float SPN=0, SPF=0, SVB=0, SB=0;
#pragma unroll
    for (int w = 0; w < 8; w++) { SPN += red[0][w]; SPF += red[1][w]; SVB += red[2][w]; SB += red[3][w]; }
    float a1 = SVB + SPN;            // -F_normal
    float a2 = (SB - SVB) + SPF;     // -F_flipped
    float m  = fmaxf(a1, a2);
    float lse = m + logf(expf(a1 - m) + expf(a2 - m));
    atomicAdd(&g_acc, sign * (double)(-lse));
  }
}

__global__ void final_kernel(float* out) { out[0] = (float)(g_acc / (double)BATCH); }

// ---- host ----
struct K2 { uint32_t a, b; };
static inline K2 tf_child(K2 k, uint32_t i) { K2 r; tf2x32(k.a, k.b, 0u, i, r.a, r.b); return r; }

extern "C" void kernel_launch(void* const* d_in, const int* in_sizes, int n_in,
                              void* d_out, int out_size) {
  (void)in_sizes; (void)n_in; (void)out_size;
  const float* v_data = (const float*)d_in[0];
  const float* cond   = (const float*)d_in[1];
  const float* W      = (const float*)d_in[2];
  const float* b      = (const float*)d_in[3];
  const float* c      = (const float*)d_in[4];
  const float* fc1w   = (const float*)d_in[5];
  const float* fc1b   = (const float*)d_in[6];
  const float* fc2w   = (const float*)d_in[7];
  const float* fc2b   = (const float*)d_in[8];

  K2 root = {0u, 42u};
  K2 k_u = tf_child(root, 0u), k_chain = tf_child(root, 1u);
  K2 kh[KSTEPS], kv[KSTEPS];
  for (int s = 0; s < KSTEPS; s++) {
    K2 sk = tf_child(k_chain, (uint32_t)s);
    kh[s] = tf_child(sk, 0u);
    kv[s] = tf_child(sk, 2u);   // ku (index 1) unused: loss is u-invariant
  }

  cudaFuncSetAttribute(gemm_mma<1, true , true >, cudaFuncAttributeMaxDynamicSharedMemorySize, SM_TOTAL);
  cudaFuncSetAttribute(gemm_mma<1, false, false>, cudaFuncAttributeMaxDynamicSharedMemorySize, SM_TOTAL);
  cudaFuncSetAttribute(gemm_mma<2, false, false>, cudaFuncAttributeMaxDynamicSharedMemorySize, SM_TOTAL);
  cudaFuncSetAttribute(gemm_mma<4, false, false>, cudaFuncAttributeMaxDynamicSharedMemorySize, SM_TOTAL);

  // streams/events created on first call (the correctness run, outside capture)
  static cudaStream_t st[NHALF] = {};
  static cudaEvent_t  evFork = nullptr, evJoin[NHALF] = {};
  if (st[0] == nullptr) {
    for (int h = 0; h < NHALF; h++) {
      cudaStreamCreateWithFlags(&st[h], cudaStreamNonBlocking);
      cudaEventCreateWithFlags(&evJoin[h], cudaEventDisableTiming);
    }
    cudaEventCreateWithFlags(&evFork, cudaEventDisableTiming);
  }

  dim3 ggh(NH / 128, HROWS / 128);   // (8, 64) = 512 CTAs per half-GEMM

  // setup (launch stream)
  biases_kernel<<<BATCH / BT_ROWS, 256>>>(cond, b, c, fc1w, fc1b, fc2w, fc2b);
  splitT_kernel<<<dim3(32, 32), dim3(32, 8)>>>(W);
  colsum_kernel<<<NH / 256, 256>>>(W);
  copyv_kernel<<<(BATCH * NV / 4) / 256, 256>>>(v_data);
  u0_kernel<<<BATCH / 256, 256>>>(k_u.a, k_u.b);

  // fork: both halves' chains are fully independent
  cudaEventRecord(evFork, 0);
  for (int h = 0; h < NHALF; h++) cudaStreamWaitEvent(st[h], evFork, 0);

  for (int h = 0; h < NHALF; h++) {
    int yb = h * (HROWS / 128);
    cudaStream_t s_ = st[h];
    for (int s = 0; s < KSTEPS; s++) {
      if (s == 0) gemm_mma<1, true , true ><<<ggh, 256, SM_TOTAL, s_>>>(kh[s].a, kh[s].b, yb);
      else        gemm_mma<1, false, false><<<ggh, 256, SM_TOTAL, s_>>>(kh[s].a, kh[s].b, yb);
      gemm_mma<2, false, false><<<ggh, 256, SM_TOTAL, s_>>>(kv[s].a, kv[s].b, yb);
    }
    fe_kernel<false, 0><<<HROWS, 256, 0, s_>>>(v_data, +1.0, h * HROWS);
    gemm_mma<4, false, false><<<ggh, 256, SM_TOTAL, s_>>>(0u, 0u, yb);
    fe_kernel<true, 1><<<HROWS, 256, 0, s_>>>(nullptr, -1.0, h * HROWS);
    cudaEventRecord(evJoin[h], s_);
  }

  // join
  for (int h = 0; h < NHALF; h++) cudaStreamWaitEvent(0, evJoin[h], 0);
  final_kernel<<<1, 1>>>((float*)d_out);
}

// round 17
// speedup vs baseline: 3.5932x; 1.0116x over previous
#include <cuda_runtime.h>
#include <cuda_bf16.h>
#include <cstdint>
#include <cmath>

#define BATCH 16384
#define NV 1024
#define NH 1024
#define HD 64
#define KSTEPS 10
#define NHALF 2
#define HROWS (BATCH / NHALF)          // 8192 rows per stream-half

__device__ float         g_bmod[(size_t)BATCH * NV];
__device__ float         g_cmod[(size_t)BATCH * NH];
__device__ float         g_a   [(size_t)BATCH * NV];   // vW of v_model (MODE 4 only)
__device__ float         g_vwd [(size_t)BATCH * NV];   // recovered v_data@W for FE-data
__device__ __nv_bfloat16 g_vb  [(size_t)BATCH * NV];   // v_data, then vbn chain state
__device__ __nv_bfloat16 g_hb  [(size_t)BATCH * NH];
__device__ float         g_u   [BATCH];                // u0 only (loss is u-invariant)
__device__ __nv_bfloat16 g_Whi[NV*NH], g_Wlo[NV*NH];   // [v][h] (k=h contiguous)
__device__ __nv_bfloat16 g_Thi[NV*NH], g_Tlo[NV*NH];   // [h][v] (k=v contiguous)
__device__ float         g_colsum[NH];
__device__ double        g_acc;

__host__ __device__ __forceinline__ void tf2x32(uint32_t k0, uint32_t k1,
                                                uint32_t x0, uint32_t x1,
                                                uint32_t& o0, uint32_t& o1) {
  uint32_t ks2 = k0 ^ k1 ^ 0x1BD11BDAu;
#define TF_R(r) { x0 += x1; x1 = (x1 << (r)) | (x1 >> (32 - (r))); x1 ^= x0; }
  x0 += k0; x1 += k1;
  TF_R(13) TF_R(15) TF_R(26) TF_R(6)   x0 += k1;  x1 += ks2 + 1u;
  TF_R(17) TF_R(29) TF_R(16) TF_R(24)  x0 += ks2; x1 += k0 + 2u;
  TF_R(13) TF_R(15) TF_R(26) TF_R(6)   x0 += k0;  x1 += k1 + 3u;
  TF_R(17) TF_R(29) TF_R(16) TF_R(24)  x0 += k1;  x1 += ks2 + 4u;
  TF_R(13) TF_R(15) TF_R(26) TF_R(6)   x0 += ks2; x1 += k0 + 5u;
#undef TF_R
  o0 = x0; o1 = x1;
}
__device__ __forceinline__ float jax_uniform(uint32_t ka, uint32_t kb, uint32_t idx) {
  uint32_t o0, o1; tf2x32(ka, kb, 0u, idx, o0, o1);
  return __uint_as_float(((o0 ^ o1) >> 9) | 0x3f800000u) - 1.0f;
}
__device__ __forceinline__ float sigmoidf_(float x)  { return 1.0f / (1.0f + expf(-x)); }
__device__ __forceinline__ float softplusf_(float x) { return fmaxf(x, 0.0f) + log1pf(expf(-fabsf(x))); }

__device__ __forceinline__ uint32_t smem_to_u32(const void* p) {
  uint32_t a;
  asm("{ .reg .u64 t; cvta.to.shared.u64 t, %1; cvt.u32.u64 %0, t; }" : "=r"(a) : "l"(p));
  return a;
}
__device__ __forceinline__ void sts128(uint32_t a, uint4 v) {
  asm volatile("st.shared.v4.b32 [%0], {%1,%2,%3,%4};" :: "r"(a), "r"(v.x), "r"(v.y), "r"(v.z), "r"(v.w) : "memory");
}
#define LDSM_X4(r0, r1, r2, r3, addr) \
  asm volatile("ldmatrix.sync.aligned.m8n8.x4.shared.b16 {%0,%1,%2,%3}, [%4];" \
    : "=r"(r0), "=r"(r1), "=r"(r2), "=r"(r3) : "r"(addr))

// ---------------- bf16 mma GEMM ----------------
// Tile 128x128, 16 k-blocks of 64, W = Whi + Wlo (2-way bf16 split), 2 CTAs/SM
// Single sync per k-block (round-9-validated ordering: all smem writes after it).
// MODE 1: A=g_vb (FLIP: xor by u), B=T* -> sample h into g_hb (S0: recover vdata@W -> g_vwd)
// MODE 2: A=g_hb, B=W* -> sample vbn into g_vb (reads g_bmod)
// MODE 4: A=g_vb, B=T* -> write g_a (for FE-model)
#define NKB 16
#define ASTR 144                       // bytes per 64-elem row (72 bf16, padded)
#define TILE_B (128 * ASTR)            // 18432
#define SM_TOTAL (6 * TILE_B)          // 110592: A0,A1,Bhi0,Bhi1,Blo0,Blo1

template<int MODE, bool S0, bool FLIP>
__global__ void __launch_bounds__(256, 2) gemm_mma(uint32_t ka, uint32_t kb, int ybase) {
  extern __shared__ char smem[];
  uint32_t sbase = smem_to_u32(smem);
  int tid = threadIdx.x, lane = tid & 31, wid = tid >> 5;
  int wm = wid & 1, wn = wid >> 1;             // warp grid 2(M) x 4(N)
  int gq = lane >> 2, tg = lane & 3;
  int bm = (blockIdx.y + ybase) * 128, bn = blockIdx.x * 128;

  const __nv_bfloat16* A  = (MODE == 2) ? g_hb : g_vb;
  const __nv_bfloat16* Bh = (MODE == 2) ? g_Whi : g_Thi;
  const __nv_bfloat16* Bl = (MODE == 2) ? g_Wlo : g_Tlo;

  int lrow[4]; uint32_t uxr[4];
#pragma unroll
  for (int q = 0; q < 4; q++) {
    lrow[q] = (tid >> 3) + 32 * q;
    uxr[q] = 0u;
    if (FLIP) uxr[q] = (g_u[bm + lrow[q]] == 0.0f) ? 0x3F803F80u : 0u;
  }
  int seg = tid & 7;

  uint4 aregs[4];
  auto ldgA = [&](int kbk) {
    int kin = kbk * 64;
#pragma unroll
    for (int q = 0; q < 4; q++) {
      uint4 v = *(const uint4*)(A + (((size_t)(bm + lrow[q])) << 10) + kin + seg * 8);
      if (FLIP) { v.x ^= uxr[q]; v.y ^= uxr[q]; v.z ^= uxr[q]; v.w ^= uxr[q]; }
      aregs[q] = v;
    }
  };
  auto stsA = [&](int buf) {
    uint32_t base = sbase + buf * TILE_B;
#pragma unroll
    for (int q = 0; q < 4; q++)
      sts128(base + lrow[q] * ASTR + seg * 16, aregs[q]);
  };
  auto issueB = [&](int kbk) {
    int kin = kbk * 64, buf = kbk & 1;
    uint32_t bh = sbase + (2 + buf) * TILE_B;
    uint32_t bl = sbase + (4 + buf) * TILE_B;
#pragma unroll
    for (int q = 0; q < 4; q++) {
      uint32_t soff = lrow[q] * ASTR + seg * 16;
      size_t goff = (((size_t)(bn + lrow[q])) << 10) + kin + seg * 8;
      asm volatile("cp.async.cg.shared.global [%0], [%1], 16;" :: "r"(bh + soff), "l"((const void*)(Bh + goff)) : "memory");
      asm volatile("cp.async.cg.shared.global [%0], [%1], 16;" :: "r"(bl + soff), "l"((const void*)(Bl + goff)) : "memory");
    }
    asm volatile("cp.async.commit_group;" ::: "memory");
  };

  float acc[4][4][4];
#pragma unroll
  for (int i = 0; i < 4; i++)
#pragma unroll
    for (int j = 0; j < 4; j++)
#pragma unroll
      for (int q = 0; q < 4; q++) acc[i][j][q] = 0.f;

  // prologue
  ldgA(0); stsA(0);
  issueB(0);
  ldgA(1);

  uint32_t a_l15 = (uint32_t)(lane & 15), a_hi16 = (uint32_t)((lane >> 4) << 4);
  uint32_t b_row = (uint32_t)((lane & 7) + ((lane >> 4) << 3));
  uint32_t b_k16 = (uint32_t)(((lane >> 3) & 1) << 4);

  for (int kbk = 0; kbk < NKB; kbk++) {
    asm volatile("cp.async.wait_group 0;" ::: "memory");
    __syncthreads();                      // single sync; ALL writes below are after it
    if (kbk + 1 < NKB) { issueB(kbk + 1); stsA((kbk + 1) & 1); }
    if (kbk + 2 < NKB) ldgA(kbk + 2);

    uint32_t Ab  = sbase + (kbk & 1) * TILE_B;
    uint32_t Bhb = sbase + (2 + (kbk & 1)) * TILE_B;
    uint32_t Blb = sbase + (4 + (kbk & 1)) * TILE_B;
#pragma unroll
    for (int ks = 0; ks < 4; ks++) {
      uint32_t afr[4][4];
#pragma unroll
      for (int i = 0; i < 4; i++) {
        uint32_t addr = Ab + (uint32_t)(wm * 64 + i * 16) * ASTR + a_l15 * ASTR + (uint32_t)(ks * 32) + a_hi16;
        LDSM_X4(afr[i][0], afr[i][1], afr[i][2], afr[i][3], addr);
      }
      uint32_t bhf[4][2], blf[4][2];
#pragma unroll
      for (int jp = 0; jp < 2; jp++) {
        uint32_t rowoff = ((uint32_t)(wn * 32 + jp * 16) + b_row) * ASTR + (uint32_t)(ks * 32) + b_k16;
        LDSM_X4(bhf[2*jp][0], bhf[2*jp][1], bhf[2*jp+1][0], bhf[2*jp+1][1], Bhb + rowoff);
        LDSM_X4(blf[2*jp][0], blf[2*jp][1], blf[2*jp+1][0], blf[2*jp+1][1], Blb + rowoff);
      }
#pragma unroll
      for (int i = 0; i < 4; i++)
#pragma unroll
        for (int j = 0; j < 4; j++)
          asm volatile("mma.sync.aligned.m16n8k16.row.col.f32.bf16.bf16.f32 "
            "{%0,%1,%2,%3}, {%4,%5,%6,%7}, {%8,%9}, {%0,%1,%2,%3};"
            : "+f"(acc[i][j][0]), "+f"(acc[i][j][1]), "+f"(acc[i][j][2]), "+f"(acc[i][j][3])
            : "r"(afr[i][0]), "r"(afr[i][1]), "r"(afr[i][2]), "r"(afr[i][3]),
              "r"(bhf[j][0]), "r"(bhf[j][1]));
#pragma unroll
      for (int i = 0; i < 4; i++)
#pragma unroll
        for (int j = 0; j < 4; j++)
          asm volatile("mma.sync.aligned.m16n8k16.row.col.f32.bf16.bf16.f32 "
            "{%0,%1,%2,%3}, {%4,%5,%6,%7}, {%8,%9}, {%0,%1,%2,%3};"
            : "+f"(acc[i][j][0]), "+f"(acc[i][j][1]), "+f"(acc[i][j][2]), "+f"(acc[i][j][3])
            : "r"(afr[i][0]), "r"(afr[i][1]), "r"(afr[i][2]), "r"(afr[i][3]),
              "r"(blf[j][0]), "r"(blf[j][1]));
    }
  }

  // epilogue
#pragma unroll
  for (int i = 0; i < 4; i++) {
    int row0 = bm + wm * 64 + i * 16 + gq;
#pragma unroll
    for (int j = 0; j < 4; j++) {
      int col = bn + wn * 32 + j * 8 + tg * 2;
#pragma unroll
      for (int half = 0; half < 2; half++) {
        int r = row0 + half * 8;
        uint32_t idx = ((uint32_t)r << 10) | (uint32_t)col;
        float v0 = acc[i][j][half * 2], v1 = acc[i][j][half * 2 + 1];
        if (MODE == 1) {
          if (S0) {   // recover vdata@W: u=1 -> D ; u=0 -> colsum - D
            float uu = g_u[r];
            float w0 = (uu != 0.0f) ? v0 : g_colsum[col]     - v0;
            float w1 = (uu != 0.0f) ? v1 : g_colsum[col + 1] - v1;
            *(float2*)(g_vwd + idx) = make_float2(w0, w1);
          }
          float2 cm = *(const float2*)(g_cmod + idx);
          float p0 = sigmoidf_(v0 + cm.x), p1 = sigmoidf_(v1 + cm.y);
          float u0 = jax_uniform(ka, kb, idx), u1 = jax_uniform(ka, kb, idx + 1);
          __nv_bfloat162 hv;
          hv.x = __float2bfloat16((u0 < p0) ? 1.0f : 0.0f);
          hv.y = __float2bfloat16((u1 < p1) ? 1.0f : 0.0f);
          *(__nv_bfloat162*)(g_hb + idx) = hv;
        } else if (MODE == 2) {
          // vbn = Bernoulli(sigmoid(a + b_mod)); u-flip cancels in next step, loss u-invariant
          float2 bm2 = *(const float2*)(g_bmod + idx);
          float p0 = sigmoidf_(v0 + bm2.x), p1 = sigmoidf_(v1 + bm2.y);
          float u0 = jax_uniform(ka, kb, idx), u1 = jax_uniform(ka, kb, idx + 1);
          __nv_bfloat162 vv;
          vv.x = __float2bfloat16((u0 < p0) ? 1.0f : 0.0f);
          vv.y = __float2bfloat16((u1 < p1) ? 1.0f : 0.0f);
          *(__nv_bfloat162*)(g_vb + idx) = vv;
        } else {
          *(float2*)(g_a + idx) = make_float2(v0, v1);
        }
      }
    }
  }
}

// ---- hypernetwork biases (row-range [r0base, r0base + HROWS)) ----
#define BT_ROWS 16
__global__ void biases_kernel(const float* __restrict__ cond, const float* __restrict__ b,
                              const float* __restrict__ c, const float* __restrict__ fc1w,
                              const float* __restrict__ fc1b, const float* __restrict__ fc2w,
                              const float* __restrict__ fc2b, int r0base) {
  __shared__ float xs[BT_ROWS][HD];
  int r0 = r0base + blockIdx.x * BT_ROWS, tid = threadIdx.x;
  for (int t = tid; t < BT_ROWS * HD; t += blockDim.x) {
    int r = t / HD, d = t % HD;
    xs[r][d] = tanhf(cond[r0 + r] * fc1w[d] + fc1b[d]);
  }
  __syncthreads();
  for (int j = tid; j < NV + NH; j += blockDim.x) {
    int gw, bw;
    if (j < NV) { gw = j; bw = NV + j; } else { gw = 2*NV + (j-NV); bw = 2*NV + NH + (j-NV); }
    const float* wg = fc2w + (size_t)gw * HD;
    const float* wb = fc2w + (size_t)bw * HD;
    float accG[BT_ROWS], accB[BT_ROWS];
#pragma unroll
    for (int r = 0; r < BT_ROWS; r++) { accG[r] = 0.f; accB[r] = 0.f; }
    for (int d = 0; d < HD; d++) {
      float g = wg[d], bb = wb[d];
#pragma unroll
      for (int r = 0; r < BT_ROWS; r++) { float x = xs[r][d]; accG[r] += g*x; accB[r] += bb*x; }
    }
    float gb = fc2b[gw], bbia = fc2b[bw];
    if (j < NV) {
      float bj = b[j];
      for (int r = 0; r < BT_ROWS; r++)
        g_bmod[(size_t)(r0 + r)*NV + j] = (1.0f + accG[r] + gb)*bj + (accB[r] + bbia);
    } else {
      int hh = j - NV; float ch = c[hh];
      for (int r = 0; r < BT_ROWS; r++)
        g_cmod[(size_t)(r0 + r)*NH + hh] = (1.0f + accG[r] + gb)*ch + (accB[r] + bbia);
    }
  }
}

// ---- W 2-way split, both layouts ----
__device__ __forceinline__ void split2(float w, __nv_bfloat16& hi, __nv_bfloat16& lo) {
  hi = __float2bfloat16(w);
  lo = __float2bfloat16(w - __bfloat162float(hi));
}
__global__ void splitT_kernel(const float* __restrict__ W) {
  __shared__ float t[32][33];
  int bx = blockIdx.x*32, by = blockIdx.y*32;
  int tx = threadIdx.x, ty = threadIdx.y;
  for (int i = 0; i < 32; i += 8) {
    int r = by + ty + i, cc = bx + tx;
    float w = W[(size_t)r*NH + cc];
    t[ty + i][tx] = w;
    __nv_bfloat16 hi, lo; split2(w, hi, lo);
    size_t ix = (size_t)r*NH + cc;
    g_Whi[ix] = hi; g_Wlo[ix] = lo;
  }
  __syncthreads();
  for (int i = 0; i < 32; i += 8) {
    float w = t[tx][ty + i];
    __nv_bfloat16 hi, lo; split2(w, hi, lo);
    size_t ix = (size_t)(bx + ty + i)*NV + by + tx;
    g_Thi[ix] = hi; g_Tlo[ix] = lo;
  }
}

// ---- zero colsum + g_acc (stream0, before colsum atomics and any FE) ----
__global__ void zeroinit_kernel() {
  int i = blockIdx.x * blockDim.x + threadIdx.x;
  if (i < NH) g_colsum[i] = 0.f;
  if (i == 0) g_acc = 0.0;
}

// ---- parallel colsum: grid (NH/256, 16); 64-row coalesced partials + atomicAdd ----
__global__ void colsum_kernel(const float* __restrict__ W) {
  int h = blockIdx.x * 256 + threadIdx.x;
  int v0 = blockIdx.y * 64;
  float s = 0.f;
  for (int r = 0; r < 64; r++) s += W[(size_t)(v0 + r)*NH + h];
  atomicAdd(&g_colsum[h], s);
}

__global__ void copyv_kernel(const float* __restrict__ v_data, int ebase) {
  int i = ebase + blockIdx.x * blockDim.x + threadIdx.x;   // float4 index
  float4 v = ((const float4*)v_data)[i];
  ushort4 o;
  o.x = __bfloat16_as_ushort(__float2bfloat16(v.x));
  o.y = __bfloat16_as_ushort(__float2bfloat16(v.y));
  o.z = __bfloat16_as_ushort(__float2bfloat16(v.z));
  o.w = __bfloat16_as_ushort(__float2bfloat16(v.w));
  ((ushort4*)g_vb)[i] = o;
}
__global__ void u0_kernel(uint32_t ka, uint32_t kb, int rbase) {
  int i = rbase + blockIdx.x * blockDim.x + threadIdx.x;
  g_u[i] = (jax_uniform(ka, kb, (uint32_t)i) < 0.5f) ? 1.0f : 0.0f;
}

// ---- free energy (rbase: row offset for stream-half) ----
template<bool USE_GV, int WSRC>
__global__ void fe_kernel(const float* __restrict__ vparam, double sign, int rbase) {
  int row = blockIdx.x + rbase, tid = threadIdx.x, wrp = tid >> 5, lane = tid & 31;
  const float* br = g_bmod + (size_t)row*NV;
  const float* wr = (WSRC == 0 ? g_vwd : g_a) + (size_t)row*NH;
  const float* cr = g_cmod + (size_t)row*NH;
  float spn = 0, spf = 0, svb = 0, sb = 0;
  for (int j = tid; j < NV; j += 256) {
    float vv = USE_GV ? __bfloat162float(g_vb[(size_t)row*NV + j]) : vparam[(size_t)row*NV + j];
    float bbv = br[j];
    svb += vv*bbv; sb += bbv;
    float w = wr[j], cm = cr[j];
    spn += softplusf_(w + cm);
    spf += softplusf_(g_colsum[j] - w + cm);
  }
#pragma unroll
  for (int o = 16; o > 0; o >>= 1) {
    spn += __shfl_down_sync(0xffffffffu, spn, o);
    spf += __shfl_down_sync(0xffffffffu, spf, o);
    svb += __shfl_down_sync(0xffffffffu, svb, o);
    sb  += __shfl_down_sync(0xffffffffu, sb,  o);
  }
  __shared__ float red[4][8];
  if (lane == 0) { red[0][wrp] = spn; red[1][wrp] = spf; red[2][wrp] = svb; red[3][wrp] = sb; }
  __syncthreads();
  if (tid == 0) {
    float SPN=0, SPF=0, SVB=0, SB=0;
#pragma unroll
    for (int w = 0; w < 8; w++) { SPN += red[0][w]; SPF += red[1][w]; SVB += red[2][w]; SB += red[3][w]; }
    float a1 = SVB + SPN;            // -F_normal
    float a2 = (SB - SVB) + SPF;     // -F_flipped
    float m  = fmaxf(a1, a2);
    float lse = m + logf(expf(a1 - m) + expf(a2 - m));
    atomicAdd(&g_acc, sign * (double)(-lse));
  }
}

__global__ void final_kernel(float* out) { out[0] = (float)(g_acc / (double)BATCH); }

// ---- host ----
struct K2 { uint32_t a, b; };
static inline K2 tf_child(K2 k, uint32_t i) { K2 r; tf2x32(k.a, k.b, 0u, i, r.a, r.b); return r; }

extern "C" void kernel_launch(void* const* d_in, const int* in_sizes, int n_in,
                              void* d_out, int out_size) {
  (void)in_sizes; (void)n_in; (void)out_size;
  const float* v_data = (const float*)d_in[0];
  const float* cond   = (const float*)d_in[1];
  const float* W      = (const float*)d_in[2];
  const float* b      = (const float*)d_in[3];
  const float* c      = (const float*)d_in[4];
  const float* fc1w   = (const float*)d_in[5];
  const float* fc1b   = (const float*)d_in[6];
  const float* fc2w   = (const float*)d_in[7];
  const float* fc2b   = (const float*)d_in[8];

  K2 root = {0u, 42u};
  K2 k_u = tf_child(root, 0u), k_chain = tf_child(root, 1u);
  K2 kh[KSTEPS], kv[KSTEPS];
  for (int s = 0; s < KSTEPS; s++) {
    K2 sk = tf_child(k_chain, (uint32_t)s);
    kh[s] = tf_child(sk, 0u);
    kv[s] = tf_child(sk, 2u);   // ku (index 1) unused: loss is u-invariant
  }

  cudaFuncSetAttribute(gemm_mma<1, true , true >, cudaFuncAttributeMaxDynamicSharedMemorySize, SM_TOTAL);
  cudaFuncSetAttribute(gemm_mma<1, false, false>, cudaFuncAttributeMaxDynamicSharedMemorySize, SM_TOTAL);
  cudaFuncSetAttribute(gemm_mma<2, false, false>, cudaFuncAttributeMaxDynamicSharedMemorySize, SM_TOTAL);
  cudaFuncSetAttribute(gemm_mma<4, false, false>, cudaFuncAttributeMaxDynamicSharedMemorySize, SM_TOTAL);

  // streams/events created on first call (the correctness run, outside capture)
  static cudaStream_t st[NHALF] = {};
  static cudaEvent_t  evFork = nullptr, evW = nullptr, evJoin[NHALF] = {};
  if (st[0] == nullptr) {
    for (int h = 0; h < NHALF; h++) {
      cudaStreamCreateWithFlags(&st[h], cudaStreamNonBlocking);
      cudaEventCreateWithFlags(&evJoin[h], cudaEventDisableTiming);
    }
    cudaEventCreateWithFlags(&evFork, cudaEventDisableTiming);
    cudaEventCreateWithFlags(&evW, cudaEventDisableTiming);
  }

  dim3 ggh(NH / 128, HROWS / 128);   // (8, 64) = 512 CTAs per half-GEMM

  // fork FIRST: side streams do their half of row-wise setup concurrently with W-prep
  cudaEventRecord(evFork, 0);
  for (int h = 0; h < NHALF; h++) {
    cudaStreamWaitEvent(st[h], evFork, 0);
    biases_kernel<<<HROWS / BT_ROWS, 256, 0, st[h]>>>(cond, b, c, fc1w, fc1b, fc2w, fc2b, h * HROWS);
    copyv_kernel<<<(HROWS * NV / 4) / 256, 256, 0, st[h]>>>(v_data, h * (HROWS * NV / 4));
    u0_kernel<<<HROWS / 256, 256, 0, st[h]>>>(k_u.a, k_u.b, h * HROWS);
  }

  // W-prep on stream0 (overlaps the above)
  zeroinit_kernel<<<4, 256>>>();
  splitT_kernel<<<dim3(32, 32), dim3(32, 8)>>>(W);
  colsum_kernel<<<dim3(NH / 256, 16), 256>>>(W);
  cudaEventRecord(evW, 0);

  for (int h = 0; h < NHALF; h++) {
    cudaStreamWaitEvent(st[h], evW, 0);
    int yb = h * (HROWS / 128);
    cudaStream_t s_ = st[h];
    for (int s = 0; s < KSTEPS; s++) {
      if (s == 0) gemm_mma<1, true , true ><<<ggh, 256, SM_TOTAL, s_>>>(kh[s].a, kh[s].b, yb);
      else        gemm_mma<1, false, false><<<ggh, 256, SM_TOTAL, s_>>>(kh[s].a, kh[s].b, yb);
      gemm_mma<2, false, false><<<ggh, 256, SM_TOTAL, s_>>>(kv[s].a, kv[s].b, yb);
    }
    fe_kernel<false, 0><<<HROWS, 256, 0, s_>>>(v_data, +1.0, h * HROWS);
    gemm_mma<4, false, false><<<ggh, 256, SM_TOTAL, s_>>>(0u, 0u, yb);
    fe_kernel<true, 1><<<HROWS, 256, 0, s_>>>(nullptr, -1.0, h * HROWS);
    cudaEventRecord(evJoin[h], s_);
  }

  // join
  for (int h = 0; h < NHALF; h++) cudaStreamWaitEvent(0, evJoin[h], 0);
  final_kernel<<<1, 1>>>((float*)d_out);
}